// round 7
// baseline (speedup 1.0000x reference)
#include <cuda_runtime.h>
#include <cuda_fp16.h>
#include <math.h>

// Problem constants
#define Nn 256   // nodes
#define Tt 256   // features
#define Bb 64    // batch
#define Dd 64    // emb dim
#define Kk 16    // top-k neighbors

// Scratch (static device globals: no allocation)
__device__ int   g_nbr[Nn * Kk];
__device__ float g_coef[Nn * Kk];
// fp16 (rounded) g = A@x, stored as pre-swizzled SW128 tile images:
// tile index = (mtile 0..127, kchunk 0..3); each tile 128 rows x 64 cols fp16 = 16KB
__device__ __align__(16) __half g_ah[Bb * Nn * Tt];   // 8 MB
// fp16 hi/lo split of W^T ([N=256 rows][K], k-chunks of 64), swizzled tiles (32KB/chunk)
__device__ __align__(16) __half g_bh[Tt * Tt];        // 128 KB
__device__ __align__(16) __half g_bl[Tt * Tt];        // 128 KB

__device__ __forceinline__ unsigned swz(unsigned o) { return o ^ ((o >> 3) & 0x70); }

__device__ __forceinline__ unsigned smem_u32(const void* p) {
    unsigned a;
    asm("{ .reg .u64 t; cvta.to.shared.u64 t, %1; cvt.u32.u64 %0, t; }" : "=r"(a) : "l"(p));
    return a;
}

// ---------------------------------------------------------------------------
// Kernel 1: graph build (blocks 0..255: one destination row i per block)
//           + W prep (blocks 256..319).
// Graph: emb transposed into smem; per-thread dot+norm; parallel top-16 via
// rank counting (rank = #greater + #equal-with-lower-index; selected iff
// rank<16; rank == position, matching lax.top_k tie-break). Selected threads
// compute hard-gumbel gates. coef = 0.0625 * gate (deg==16 structurally).
// ---------------------------------------------------------------------------
#define EST_STRIDE 257
#define GRAPH_SMEM ((Dd * EST_STRIDE + 2 * Nn) * 4)   // esT + sval + ssq ~ 67.8KB

__global__ __launch_bounds__(256) void graph_kernel(
    const float* __restrict__ emb,
    const float* __restrict__ logits,
    const float* __restrict__ gu,
    const float* __restrict__ W)
{
    const int tid = threadIdx.x;

    if (blockIdx.x >= Nn) {
        // ---- W prep: 64 blocks x 1024 elements ----
        #pragma unroll
        for (int t = 0; t < 4; t++) {
            int idx = (blockIdx.x - Nn) * 1024 + tid + 256 * t;   // 0..65535
            int n = idx & 255;
            int k = idx >> 8;
            float val = W[k * 256 + n];
            __half hi = __float2half_rn(val);
            __half lo = __float2half_rn(val - __half2float(hi));
            int kc = k >> 6, cc = k & 63;
            unsigned off = swz((unsigned)(n * 128 + cc * 2));
            size_t base = (size_t)kc * 32768 + off;
            *(__half*)((char*)g_bh + base) = hi;
            *(__half*)((char*)g_bl + base) = lo;
        }
        return;
    }

    extern __shared__ float smf[];
    float* esT  = smf;                         // [64][257]
    float* sval = smf + Dd * EST_STRIDE;       // [256], 16B-aligned
    float* ssq  = sval + Nn;                   // [256]

    const int i = blockIdx.x;

    // load emb transposed: esT[d][j] = emb[j][d]; conflict-free writes (pad 257)
    #pragma unroll
    for (int t = 0; t < 64; t++) {
        int lin = tid + 256 * t;          // = j*64 + d
        int j = lin >> 6, d = lin & 63;
        esT[d * EST_STRIDE + j] = emb[lin];
    }
    __syncthreads();

    // per-thread dot(emb[i], emb[tid]) and ||emb[tid]||^2
    float dot = 0.f, ss = 0.f;
    #pragma unroll
    for (int d = 0; d < Dd; d++) {
        float v  = esT[d * EST_STRIDE + tid];   // conflict-free
        float vi = esT[d * EST_STRIDE + i];     // broadcast
        ss  += v * v;
        dot += v * vi;
    }
    ssq[tid] = ss;
    __syncthreads();
    const float v = dot / (sqrtf(ssq[i]) * sqrtf(ss));
    sval[tid] = v;
    __syncthreads();

    // rank by counting (float4 reads, all broadcast)
    int cnt = 0;
    const float4* sv4 = (const float4*)sval;
    #pragma unroll 8
    for (int t4 = 0; t4 < 64; t4++) {
        float4 w = sv4[t4];
        int t = t4 * 4;
        cnt += (w.x > v) || (w.x == v && (t + 0) < tid);
        cnt += (w.y > v) || (w.y == v && (t + 1) < tid);
        cnt += (w.z > v) || (w.z == v && (t + 2) < tid);
        cnt += (w.w > v) || (w.w == v && (t + 3) < tid);
    }

    if (cnt < Kk) {
        const int j = tid;
        const int e = i * Nn + j;
        float l0 = logits[2 * e], l1 = logits[2 * e + 1];
        float u0 = gu[2 * e],     u1 = gu[2 * e + 1];
        float a0 = l0 - logf(-logf(u0));
        float a1 = l1 - logf(-logf(u1));
        float m  = fmaxf(a0, a1);
        float e0 = expf(a0 - m), e1 = expf(a1 - m);
        float s0 = e0 / (e0 + e1);
        float hard = (a0 >= a1) ? 1.0f : 0.0f;
        float gate = (hard + s0) - s0;          // straight-through fp order
        g_nbr[i * Kk + cnt]  = j;
        g_coef[i * Kk + cnt] = 0.0625f * gate;  // ew == 1/16 exactly
    }
}

// ---------------------------------------------------------------------------
// Kernel 2: gather  g[b,i,:] = sum_k coef[i,k] * x[b, nbr[i,k], :]
// Grid (4 k-chunks, B). Stages x[b][:, chunk] (64KB dynamic smem) via float4;
// per warp: one row at a time, 2 cols/lane, half2 store into the pre-swizzled
// SW128 tile layout.
// ---------------------------------------------------------------------------
#define GATHER_SMEM (Nn * 64 * 4)   // 65536 bytes

__global__ __launch_bounds__(256) void gather_kernel(const float* __restrict__ x)
{
    extern __shared__ float xs[];   // [Nn][64]
    const int kc  = blockIdx.x;     // 0..3
    const int b   = blockIdx.y;
    const int tid = threadIdx.x;
    const int wid = tid >> 5;
    const int lane = tid & 31;

    const float* xb = x + (size_t)b * Nn * Tt + kc * 64;
    #pragma unroll
    for (int t = 0; t < 16; t++) {
        int idx = tid + 256 * t;
        int r = idx >> 4, c4 = idx & 15;
        *(float4*)&xs[r * 64 + c4 * 4] = *(const float4*)&xb[r * Tt + c4 * 4];
    }
    __syncthreads();

    const int c2 = lane * 2;   // column pair within the 64-col chunk
    #pragma unroll 4
    for (int it = 0; it < 32; it++) {
        int i = wid + (it << 3);
        float a0 = 0.f, a1 = 0.f;
        #pragma unroll
        for (int k = 0; k < Kk; k++) {
            int   j  = g_nbr[i * Kk + k];    // warp-uniform
            float cf = g_coef[i * Kk + k];
            float2 vv = *(const float2*)&xs[j * 64 + c2];
            a0 += cf * vv.x;
            a1 += cf * vv.y;
        }
        int m  = b * Nn + i;
        int mt = m >> 7;
        int r  = m & 127;
        unsigned off = swz((unsigned)(r * 128 + c2 * 2));
        *(__half2*)((char*)g_ah + (size_t)(mt * 4 + kc) * 16384 + off) =
            __floats2half2_rn(a0, a1);
    }
}

// ---------------------------------------------------------------------------
// Kernel 3: out = g @ W + bias via mma.sync, 2-product compensation:
//   D = Ah*Bh + Ah*Bl   (fp32 accumulate; A rounded fp16, W split hi/lo)
// BM=128, BN=128, BK=64 per stage; 8 warps, warp tile 64x32; cp.async
// double-buffered; 48KB/stage -> 96KB total -> 2 CTAs/SM.
// ---------------------------------------------------------------------------
#define STAGEB 49152
#define GSMEM  (2 * STAGEB)

#define LDSM4(r, addr) \
    asm volatile("ldmatrix.sync.aligned.m8n8.x4.shared.b16 {%0,%1,%2,%3}, [%4];" \
        : "=r"((r)[0]), "=r"((r)[1]), "=r"((r)[2]), "=r"((r)[3]) : "r"(addr))

#define MMA16816(d, a, b0, b1) \
    asm volatile("mma.sync.aligned.m16n8k16.row.col.f32.f16.f16.f32 " \
        "{%0,%1,%2,%3}, {%4,%5,%6,%7}, {%8,%9}, {%0,%1,%2,%3};" \
        : "+f"((d)[0]), "+f"((d)[1]), "+f"((d)[2]), "+f"((d)[3]) \
        : "r"((a)[0]), "r"((a)[1]), "r"((a)[2]), "r"((a)[3]), "r"(b0), "r"(b1))

__global__ __launch_bounds__(256, 2) void gemm_kernel(
    const float* __restrict__ bias, float* __restrict__ out)
{
    extern __shared__ unsigned char sm[];
    const unsigned sb = smem_u32(sm);
    const int tid  = threadIdx.x;
    const int lane = tid & 31;
    const int wid  = tid >> 5;
    const int mt   = blockIdx.x;   // 0..127
    const int nt   = blockIdx.y;   // 0..1
    const int wm   = wid >> 2;     // 0..1 (64 rows each)
    const int wn   = wid & 3;      // 0..3 (32 cols each)

    const char* aH = (const char*)g_ah + (size_t)mt * 65536;
    const char* bH = (const char*)g_bh + (size_t)nt * 16384;
    const char* bL = (const char*)g_bl + (size_t)nt * 16384;

    // stage fill: pure linear 16B copies (tiles are pre-swizzled in gmem)
    auto load_stage = [&](int st, int c) {
        const unsigned d = sb + st * STAGEB;
        const char* srcs[3] = { aH + c * 16384, bH + c * 32768, bL + c * 32768 };
        #pragma unroll
        for (int rgn = 0; rgn < 3; rgn++) {
            const char* s = srcs[rgn];
            const unsigned dd = d + rgn * 16384;
            #pragma unroll
            for (int t = 0; t < 4; t++) {
                const unsigned o = (unsigned)(tid + 256 * t) * 16u;
                asm volatile("cp.async.cg.shared.global [%0], [%1], 16;"
                             :: "r"(dd + o), "l"(s + o));
            }
        }
        asm volatile("cp.async.commit_group;" ::: "memory");
    };

    // per-lane ldmatrix byte offsets (pre-swizzle)
    const unsigned colSel = (lane & 16) ? 16u : 0u;
    unsigned aoff[4], boff[2];
    #pragma unroll
    for (int mf = 0; mf < 4; mf++)
        aoff[mf] = (unsigned)((wm * 64 + mf * 16 + (lane & 15)) * 128) + colSel;
    #pragma unroll
    for (int g = 0; g < 2; g++)
        boff[g] = (unsigned)((wn * 32 + g * 16 + (lane & 15)) * 128) + colSel;

    float acc[4][4][4];
    #pragma unroll
    for (int mf = 0; mf < 4; mf++)
        #pragma unroll
        for (int nf = 0; nf < 4; nf++)
            #pragma unroll
            for (int e = 0; e < 4; e++) acc[mf][nf][e] = 0.f;

    load_stage(0, 0);

    #pragma unroll 1
    for (int c = 0; c < 4; c++) {
        if (c < 3) {
            load_stage((c + 1) & 1, c + 1);
            asm volatile("cp.async.wait_group 1;" ::: "memory");
        } else {
            asm volatile("cp.async.wait_group 0;" ::: "memory");
        }
        __syncthreads();

        const unsigned base = sb + (c & 1) * STAGEB;
        #pragma unroll
        for (int ks = 0; ks < 4; ks++) {
            unsigned a_h[4][4], b_h[2][4], b_l[2][4];
            #pragma unroll
            for (int mf = 0; mf < 4; mf++) {
                LDSM4(a_h[mf], base + swz(aoff[mf] + ks * 32));
            }
            #pragma unroll
            for (int g = 0; g < 2; g++) {
                const unsigned so = swz(boff[g] + ks * 32);
                LDSM4(b_h[g], base + 16384 + so);
                LDSM4(b_l[g], base + 32768 + so);
            }
            #pragma unroll
            for (int mf = 0; mf < 4; mf++) {
                #pragma unroll
                for (int nf = 0; nf < 4; nf++) {
                    const int g = nf >> 1, p = nf & 1;
                    MMA16816(acc[mf][nf], a_h[mf], b_h[g][p], b_h[g][2 + p]);
                    MMA16816(acc[mf][nf], a_h[mf], b_l[g][p], b_l[g][2 + p]);
                }
            }
        }
        __syncthreads();
    }

    // epilogue: c0,c1 -> (row, n..n+1); c2,c3 -> (row+8, n..n+1)
    const int mbase = mt * 128 + wm * 64;
    const int nbase = nt * 128 + wn * 32;
    #pragma unroll
    for (int mf = 0; mf < 4; mf++) {
        const int m = mbase + mf * 16 + (lane >> 2);
        #pragma unroll
        for (int nf = 0; nf < 4; nf++) {
            const int n = nbase + nf * 8 + (lane & 3) * 2;
            const float b0 = bias[n], b1 = bias[n + 1];
            float2 v0 = make_float2(acc[mf][nf][0] + b0, acc[mf][nf][1] + b1);
            float2 v1 = make_float2(acc[mf][nf][2] + b0, acc[mf][nf][3] + b1);
            *(float2*)&out[(size_t)m * 256 + n]       = v0;
            *(float2*)&out[(size_t)(m + 8) * 256 + n] = v1;
        }
    }
}

// ---------------------------------------------------------------------------
extern "C" void kernel_launch(void* const* d_in, const int* in_sizes, int n_in,
                              void* d_out, int out_size)
{
    const float* x      = (const float*)d_in[0];   // [64,256,256]
    const float* emb    = (const float*)d_in[1];   // [256,64]
    const float* W      = (const float*)d_in[2];   // [256,256]
    const float* bias   = (const float*)d_in[3];   // [256]
    const float* logits = (const float*)d_in[4];   // [65536,2]
    const float* gu     = (const float*)d_in[5];   // [65536,2]
    float* out = (float*)d_out;                    // [64,256,256]

    cudaFuncSetAttribute(graph_kernel,  cudaFuncAttributeMaxDynamicSharedMemorySize, GRAPH_SMEM);
    cudaFuncSetAttribute(gather_kernel, cudaFuncAttributeMaxDynamicSharedMemorySize, GATHER_SMEM);
    cudaFuncSetAttribute(gemm_kernel,   cudaFuncAttributeMaxDynamicSharedMemorySize, GSMEM);

    graph_kernel<<<Nn + 64, 256, GRAPH_SMEM>>>(emb, logits, gu, W);
    gather_kernel<<<dim3(4, Bb), 256, GATHER_SMEM>>>(x);
    gemm_kernel<<<dim3(128, 2), 256, GSMEM>>>(bias, out);
}

// round 10
// speedup vs baseline: 1.2424x; 1.2424x over previous
#include <cuda_runtime.h>
#include <cuda_fp16.h>
#include <math.h>

// Problem constants
#define Nn 256   // nodes
#define Tt 256   // features
#define Bb 64    // batch
#define Dd 64    // emb dim
#define Kk 16    // top-k neighbors

// Scratch (static device globals: no allocation)
__device__ float g_cos[Nn * Nn];     // cosine similarity matrix, 256KB
__device__ int   g_nbr[Nn * Kk];
__device__ float g_coef[Nn * Kk];
// fp16 (rounded) g = A@x, pre-swizzled SW128 tile images:
// tile index = (mtile 0..127, kchunk 0..3); each tile 128 rows x 64 cols fp16 = 16KB
__device__ __align__(16) __half g_ah[Bb * Nn * Tt];   // 8 MB
// fp16 W^T ([N=256 rows][K], k-chunks of 64), swizzled tiles (32KB/chunk)
__device__ __align__(16) __half g_bh[Tt * Tt];        // 128 KB

__device__ __forceinline__ unsigned swz(unsigned o) { return o ^ ((o >> 3) & 0x70); }

__device__ __forceinline__ unsigned smem_u32(const void* p) {
    unsigned a;
    asm("{ .reg .u64 t; cvta.to.shared.u64 t, %1; cvt.u32.u64 %0, t; }" : "=r"(a) : "l"(p));
    return a;
}

// ---------------------------------------------------------------------------
// Kernel 1: cos matrix (blocks 0..31, 8 rows each; emb loaded ONCE per block)
//           + W prep (blocks 32..47).
// ---------------------------------------------------------------------------
#define ES4_STRIDE 17                         // float4 stride (68 floats; odd -> conflict-free)
#define COS_SMEM  ((Nn * 68 + Nn) * 4)        // es + ssq = 70656 bytes

__global__ __launch_bounds__(256) void cos_kernel(
    const float* __restrict__ emb,
    const float* __restrict__ W)
{
    const int tid = threadIdx.x;

    if (blockIdx.x >= 32) {
        // ---- W prep: 16 blocks x 4096 elements, fp16 swizzled tiles ----
        #pragma unroll
        for (int t = 0; t < 16; t++) {
            int idx = (blockIdx.x - 32) * 4096 + tid + 256 * t;   // 0..65535
            int n = idx & 255;
            int k = idx >> 8;
            __half hi = __float2half_rn(W[k * 256 + n]);
            int kc = k >> 6, cc = k & 63;
            unsigned off = swz((unsigned)(n * 128 + cc * 2));
            *(__half*)((char*)g_bh + (size_t)kc * 32768 + off) = hi;
        }
        return;
    }

    extern __shared__ float smf[];
    float4* es4 = (float4*)smf;          // [256][17] float4  (= [256][68] floats)
    float*  ssq = smf + Nn * 68;         // [256]

    const int i0 = blockIdx.x * 8;

    // coalesced load emb -> padded smem rows
    #pragma unroll
    for (int t = 0; t < 16; t++) {
        int lin4 = tid + 256 * t;        // float4 index: j*16 + d4
        int j = lin4 >> 4, d4 = lin4 & 15;
        es4[j * ES4_STRIDE + d4] = ((const float4*)emb)[lin4];
    }
    __syncthreads();

    // per-thread: dot(emb[i0+r], emb[tid]) for r=0..7, and ||emb[tid]||^2
    float dot[8];
    #pragma unroll
    for (int r = 0; r < 8; r++) dot[r] = 0.f;
    float ss = 0.f;
    #pragma unroll
    for (int d4 = 0; d4 < 16; d4++) {
        float4 a = es4[tid * ES4_STRIDE + d4];   // conflict-free (odd stride)
        ss += a.x * a.x; ss += a.y * a.y; ss += a.z * a.z; ss += a.w * a.w;
        #pragma unroll
        for (int r = 0; r < 8; r++) {
            float4 w = es4[(i0 + r) * ES4_STRIDE + d4];   // broadcast
            dot[r] += a.x * w.x; dot[r] += a.y * w.y;
            dot[r] += a.z * w.z; dot[r] += a.w * w.w;
        }
    }
    ssq[tid] = ss;
    __syncthreads();

    const float nj = sqrtf(ss);
    #pragma unroll
    for (int r = 0; r < 8; r++)
        g_cos[(i0 + r) * Nn + tid] = dot[r] / (sqrtf(ssq[i0 + r]) * nj);
}

// ---------------------------------------------------------------------------
// Kernel 2: rank + gates. One block per destination row i.
// rank(j) = #{t: cos>cos_j} + #{t<j: cos==cos_j}; selected iff rank<16;
// rank == top-k position (matches lax.top_k incl. tie-break).
// ---------------------------------------------------------------------------
__global__ __launch_bounds__(256) void rank_kernel(
    const float* __restrict__ logits,
    const float* __restrict__ gu)
{
    __shared__ float sval[Nn];
    const int i   = blockIdx.x;
    const int tid = threadIdx.x;

    sval[tid] = g_cos[i * Nn + tid];
    __syncthreads();
    const float v = sval[tid];

    int cnt = 0;
    const float4* sv4 = (const float4*)sval;
    #pragma unroll 8
    for (int t4 = 0; t4 < 64; t4++) {
        float4 w = sv4[t4];            // broadcast
        int t = t4 * 4;
        cnt += (w.x > v) || (w.x == v && (t + 0) < tid);
        cnt += (w.y > v) || (w.y == v && (t + 1) < tid);
        cnt += (w.z > v) || (w.z == v && (t + 2) < tid);
        cnt += (w.w > v) || (w.w == v && (t + 3) < tid);
    }

    if (cnt < Kk) {
        const int j = tid;
        const int e = i * Nn + j;
        float l0 = logits[2 * e], l1 = logits[2 * e + 1];
        float u0 = gu[2 * e],     u1 = gu[2 * e + 1];
        float a0 = l0 - logf(-logf(u0));
        float a1 = l1 - logf(-logf(u1));
        float m  = fmaxf(a0, a1);
        float e0 = expf(a0 - m), e1 = expf(a1 - m);
        float s0 = e0 / (e0 + e1);
        float hard = (a0 >= a1) ? 1.0f : 0.0f;
        float gate = (hard + s0) - s0;          // straight-through fp order
        g_nbr[i * Kk + cnt]  = j;
        g_coef[i * Kk + cnt] = 0.0625f * gate;  // ew == 1/16 exactly (deg==16)
    }
}

// ---------------------------------------------------------------------------
// Kernel 3: gather  g[b,i,:] = sum_k coef[i,k] * x[b, nbr[i,k], :]
// Grid (4 k-chunks, B). x chunk (64KB) + nbr (16KB) + coef (16KB) staged in
// dynamic smem; per warp one row at a time, 2 cols/lane, half2 store into the
// pre-swizzled SW128 tile layout.
// ---------------------------------------------------------------------------
#define GATHER_SMEM (Nn * 64 * 4 + Nn * Kk * 4 * 2)   // 98304 bytes

__global__ __launch_bounds__(256) void gather_kernel(const float* __restrict__ x)
{
    extern __shared__ float xs[];                 // [Nn][64]
    int*   sn = (int*)(xs + Nn * 64);             // [Nn][16]
    float* sc = (float*)(sn + Nn * Kk);           // [Nn][16]

    const int kc  = blockIdx.x;     // 0..3
    const int b   = blockIdx.y;
    const int tid = threadIdx.x;
    const int wid = tid >> 5;
    const int lane = tid & 31;

    const float* xb = x + (size_t)b * Nn * Tt + kc * 64;
    #pragma unroll
    for (int t = 0; t < 16; t++) {
        int idx = tid + 256 * t;
        int r = idx >> 4, c4 = idx & 15;
        *(float4*)&xs[r * 64 + c4 * 4] = *(const float4*)&xb[r * Tt + c4 * 4];
    }
    #pragma unroll
    for (int t = 0; t < 4; t++) {
        ((int4*)sn)[tid + 256 * t]   = ((const int4*)g_nbr)[tid + 256 * t];
        ((float4*)sc)[tid + 256 * t] = ((const float4*)g_coef)[tid + 256 * t];
    }
    __syncthreads();

    const int c2 = lane * 2;   // column pair within the 64-col chunk
    #pragma unroll 4
    for (int it = 0; it < 32; it++) {
        int i = wid + (it << 3);
        float a0 = 0.f, a1 = 0.f;
        #pragma unroll
        for (int k = 0; k < Kk; k++) {
            int   j  = sn[i * Kk + k];     // warp-uniform broadcast
            float cf = sc[i * Kk + k];
            float2 vv = *(const float2*)&xs[j * 64 + c2];
            a0 += cf * vv.x;
            a1 += cf * vv.y;
        }
        int m  = b * Nn + i;
        int mt = m >> 7;
        int r  = m & 127;
        unsigned off = swz((unsigned)(r * 128 + c2 * 2));
        *(__half2*)((char*)g_ah + (size_t)(mt * 4 + kc) * 16384 + off) =
            __floats2half2_rn(a0, a1);
    }
}

// ---------------------------------------------------------------------------
// Kernel 4: out = g @ W + bias via mma.sync, single fp16 product, fp32 accum.
// BM=128, BN=128, BK=64 per stage; 8 warps, warp tile 64x32; cp.async
// double-buffered; 32KB/stage -> 64KB total.
// ---------------------------------------------------------------------------
#define STAGEB 32768
#define GSMEM  (2 * STAGEB)

#define LDSM4(r, addr) \
    asm volatile("ldmatrix.sync.aligned.m8n8.x4.shared.b16 {%0,%1,%2,%3}, [%4];" \
        : "=r"((r)[0]), "=r"((r)[1]), "=r"((r)[2]), "=r"((r)[3]) : "r"(addr))

#define MMA16816(d, a, b0, b1) \
    asm volatile("mma.sync.aligned.m16n8k16.row.col.f32.f16.f16.f32 " \
        "{%0,%1,%2,%3}, {%4,%5,%6,%7}, {%8,%9}, {%0,%1,%2,%3};" \
        : "+f"((d)[0]), "+f"((d)[1]), "+f"((d)[2]), "+f"((d)[3]) \
        : "r"((a)[0]), "r"((a)[1]), "r"((a)[2]), "r"((a)[3]), "r"(b0), "r"(b1))

__global__ __launch_bounds__(256, 2) void gemm_kernel(
    const float* __restrict__ bias, float* __restrict__ out)
{
    extern __shared__ unsigned char sm[];
    const unsigned sb = smem_u32(sm);
    const int tid  = threadIdx.x;
    const int lane = tid & 31;
    const int wid  = tid >> 5;
    const int mt   = blockIdx.x;   // 0..127
    const int nt   = blockIdx.y;   // 0..1
    const int wm   = wid >> 2;     // 0..1 (64 rows each)
    const int wn   = wid & 3;      // 0..3 (32 cols each)

    const char* aH = (const char*)g_ah + (size_t)mt * 65536;
    const char* bH = (const char*)g_bh + (size_t)nt * 16384;

    // stage fill: pure linear 16B copies (tiles are pre-swizzled in gmem)
    auto load_stage = [&](int st, int c) {
        const unsigned d = sb + st * STAGEB;
        const char* srcs[2] = { aH + c * 16384, bH + c * 32768 };
        #pragma unroll
        for (int rgn = 0; rgn < 2; rgn++) {
            const char* s = srcs[rgn];
            const unsigned dd = d + rgn * 16384;
            #pragma unroll
            for (int t = 0; t < 4; t++) {
                const unsigned o = (unsigned)(tid + 256 * t) * 16u;
                asm volatile("cp.async.cg.shared.global [%0], [%1], 16;"
                             :: "r"(dd + o), "l"(s + o));
            }
        }
        asm volatile("cp.async.commit_group;" ::: "memory");
    };

    // per-lane ldmatrix byte offsets (pre-swizzle)
    const unsigned colSel = (lane & 16) ? 16u : 0u;
    unsigned aoff[4], boff[2];
    #pragma unroll
    for (int mf = 0; mf < 4; mf++)
        aoff[mf] = (unsigned)((wm * 64 + mf * 16 + (lane & 15)) * 128) + colSel;
    #pragma unroll
    for (int g = 0; g < 2; g++)
        boff[g] = (unsigned)((wn * 32 + g * 16 + (lane & 15)) * 128) + colSel;

    float acc[4][4][4];
    #pragma unroll
    for (int mf = 0; mf < 4; mf++)
        #pragma unroll
        for (int nf = 0; nf < 4; nf++)
            #pragma unroll
            for (int e = 0; e < 4; e++) acc[mf][nf][e] = 0.f;

    load_stage(0, 0);

    #pragma unroll 1
    for (int c = 0; c < 4; c++) {
        if (c < 3) {
            load_stage((c + 1) & 1, c + 1);
            asm volatile("cp.async.wait_group 1;" ::: "memory");
        } else {
            asm volatile("cp.async.wait_group 0;" ::: "memory");
        }
        __syncthreads();

        const unsigned base = sb + (c & 1) * STAGEB;
        #pragma unroll
        for (int ks = 0; ks < 4; ks++) {
            unsigned a_h[4][4], b_h[2][4];
            #pragma unroll
            for (int mf = 0; mf < 4; mf++)
                LDSM4(a_h[mf], base + swz(aoff[mf] + ks * 32));
            #pragma unroll
            for (int g = 0; g < 2; g++)
                LDSM4(b_h[g], base + 16384 + swz(boff[g] + ks * 32));
            #pragma unroll
            for (int mf = 0; mf < 4; mf++) {
                #pragma unroll
                for (int nf = 0; nf < 4; nf++) {
                    const int g = nf >> 1, p = nf & 1;
                    MMA16816(acc[mf][nf], a_h[mf], b_h[g][p], b_h[g][2 + p]);
                }
            }
        }
        __syncthreads();
    }

    // epilogue
    const int mbase = mt * 128 + wm * 64;
    const int nbase = nt * 128 + wn * 32;
    #pragma unroll
    for (int mf = 0; mf < 4; mf++) {
        const int m = mbase + mf * 16 + (lane >> 2);
        #pragma unroll
        for (int nf = 0; nf < 4; nf++) {
            const int n = nbase + nf * 8 + (lane & 3) * 2;
            const float b0 = bias[n], b1 = bias[n + 1];
            float2 v0 = make_float2(acc[mf][nf][0] + b0, acc[mf][nf][1] + b1);
            float2 v1 = make_float2(acc[mf][nf][2] + b0, acc[mf][nf][3] + b1);
            *(float2*)&out[(size_t)m * 256 + n]       = v0;
            *(float2*)&out[(size_t)(m + 8) * 256 + n] = v1;
        }
    }
}

// ---------------------------------------------------------------------------
extern "C" void kernel_launch(void* const* d_in, const int* in_sizes, int n_in,
                              void* d_out, int out_size)
{
    const float* x      = (const float*)d_in[0];   // [64,256,256]
    const float* emb    = (const float*)d_in[1];   // [256,64]
    const float* W      = (const float*)d_in[2];   // [256,256]
    const float* bias   = (const float*)d_in[3];   // [256]
    const float* logits = (const float*)d_in[4];   // [65536,2]
    const float* gu     = (const float*)d_in[5];   // [65536,2]
    float* out = (float*)d_out;                    // [64,256,256]

    cudaFuncSetAttribute(cos_kernel,    cudaFuncAttributeMaxDynamicSharedMemorySize, COS_SMEM);
    cudaFuncSetAttribute(gather_kernel, cudaFuncAttributeMaxDynamicSharedMemorySize, GATHER_SMEM);
    cudaFuncSetAttribute(gemm_kernel,   cudaFuncAttributeMaxDynamicSharedMemorySize, GSMEM);

    cos_kernel<<<48, 256, COS_SMEM>>>(emb, W);
    rank_kernel<<<Nn, 256>>>(logits, gu);
    gather_kernel<<<dim3(4, Bb), 256, GATHER_SMEM>>>(x);
    gemm_kernel<<<dim3(128, 2), 256, GSMEM>>>(bias, out);
}